// round 4
// baseline (speedup 1.0000x reference)
#include <cuda_runtime.h>
#include <math.h>

#define FEAT       512
#define FEAT4      128            // FEAT / 4
#define MAX_NSEG   65536
#define VPART_BLKS 32
#define E_PER_BLK  16             // FEAT / VPART_BLKS

__device__ float g_v[FEAT];
__device__ float g_vpart[VPART_BLKS * FEAT];
__device__ float g_c;
__device__ int   g_seg_start[MAX_NSEG + 1];

// ---------------------------------------------------------------------------
// Kernel A (fused setup): blocks [0, VPART_BLKS) compute partial v = W^T q;
// blocks [VPART_BLKS, ...) build segment start offsets from sorted int32 idx.
// ---------------------------------------------------------------------------
__global__ __launch_bounds__(256)
void setup_kernel(const float* __restrict__ W,
                  const float* __restrict__ q,
                  const int* __restrict__ idx,
                  int n, int nseg) {
    const int b = blockIdx.x;
    if (b < VPART_BLKS) {
        // partial mat-vec over a 16-row slice of W; 256 threads cover d in 2 steps
        #pragma unroll
        for (int half = 0; half < 2; half++) {
            const int d = threadIdx.x + half * 256;
            float acc = 0.0f;
            #pragma unroll
            for (int i = 0; i < E_PER_BLK; i++) {
                int e = b * E_PER_BLK + i;
                acc = fmaf(W[(size_t)e * FEAT + d], __ldg(&q[e]), acc);
            }
            g_vpart[b * FEAT + d] = acc;
        }
    } else {
        const int i = (b - VPART_BLKS) * 256 + threadIdx.x;
        if (i >= n) return;
        int cur  = idx[i];
        int prev = (i == 0) ? -1 : idx[i - 1];
        if (cur  > nseg) cur  = nseg;
        if (prev > nseg) prev = nseg;
        for (int s = prev + 1; s <= cur; s++) g_seg_start[s] = i;
        if (i == n - 1) {
            for (int s = cur + 1; s <= nseg; s++) g_seg_start[s] = n;
        }
    }
}

// ---------------------------------------------------------------------------
// Kernel B: reduce partials -> g_v;  c = b . q
// ---------------------------------------------------------------------------
__global__ __launch_bounds__(FEAT)
void compute_v_final_kernel(const float* __restrict__ b,
                            const float* __restrict__ q) {
    const int d = threadIdx.x;
    float acc = 0.0f;
    #pragma unroll
    for (int p = 0; p < VPART_BLKS; p++) acc += g_vpart[p * FEAT + d];
    g_v[d] = acc;

    __shared__ float red[FEAT];
    red[d] = b[d] * q[d];
    __syncthreads();
    for (int s = FEAT / 2; s > 0; s >>= 1) {
        if (d < s) red[d] += red[d + s];
        __syncthreads();
    }
    if (d == 0) g_c = red[0];
}

// ---------------------------------------------------------------------------
// Kernel C: warp-per-segment online-softmax attention pooling with row
// double-buffering: row r+1's 4 LDG.128 issue before row r's score reduction,
// overlapping the ~300-cycle compute chain with the next DRAM access.
// No __syncthreads, no atomics, features read exactly once.
// ---------------------------------------------------------------------------
#define WARPS_PER_BLK 8

__global__ __launch_bounds__(WARPS_PER_BLK * 32, 3)
void warp_pool_kernel(const float* __restrict__ feat,
                      float* __restrict__ out,
                      int nseg) {
    const int wid  = threadIdx.x >> 5;
    const int lane = threadIdx.x & 31;
    const int s    = blockIdx.x * WARPS_PER_BLK + wid;
    if (s >= nseg) return;

    const int start = g_seg_start[s];
    const int end   = g_seg_start[s + 1];

    float4* orow4 = (float4*)(out + (size_t)s * FEAT);

    if (start >= end) {
        // empty segment: segment_sum == 0
        const float4 z = make_float4(0.f, 0.f, 0.f, 0.f);
        orow4[lane] = z; orow4[32 + lane] = z; orow4[64 + lane] = z; orow4[96 + lane] = z;
        return;
    }

    // register-resident v slice
    const float4* v4 = (const float4*)g_v;
    const float4 v0 = v4[lane];
    const float4 v1 = v4[32 + lane];
    const float4 v2 = v4[64 + lane];
    const float4 v3 = v4[96 + lane];
    const float  c  = g_c;

    float m   = -INFINITY;
    float den = 0.0f;
    float4 a0 = make_float4(0.f, 0.f, 0.f, 0.f);
    float4 a1 = a0, a2 = a0, a3 = a0;

    const float4* feat4 = (const float4*)feat;

    // preload first row
    const float4* row = feat4 + (size_t)start * FEAT4;
    float4 f0 = row[lane];
    float4 f1 = row[32 + lane];
    float4 f2 = row[64 + lane];
    float4 f3 = row[96 + lane];

    for (int r = start; r < end; r++) {
        // ---- prefetch next row (issues before the shfl-reduce chain) ----
        float4 g0, g1, g2, g3;
        const bool has_next = (r + 1 < end);
        if (has_next) {
            const float4* nrow = feat4 + (size_t)(r + 1) * FEAT4;
            g0 = nrow[lane];
            g1 = nrow[32 + lane];
            g2 = nrow[64 + lane];
            g3 = nrow[96 + lane];
        }

        // ---- score = f . v  (warp allreduce) ----
        float p = f0.x * v0.x;
        p = fmaf(f0.y, v0.y, p); p = fmaf(f0.z, v0.z, p); p = fmaf(f0.w, v0.w, p);
        p = fmaf(f1.x, v1.x, p); p = fmaf(f1.y, v1.y, p); p = fmaf(f1.z, v1.z, p); p = fmaf(f1.w, v1.w, p);
        p = fmaf(f2.x, v2.x, p); p = fmaf(f2.y, v2.y, p); p = fmaf(f2.z, v2.z, p); p = fmaf(f2.w, v2.w, p);
        p = fmaf(f3.x, v3.x, p); p = fmaf(f3.y, v3.y, p); p = fmaf(f3.z, v3.z, p); p = fmaf(f3.w, v3.w, p);

        #pragma unroll
        for (int o = 16; o > 0; o >>= 1)
            p += __shfl_xor_sync(0xffffffffu, p, o);

        // ---- online softmax update ----
        const float sc    = p + c;
        const float mn    = fmaxf(m, sc);
        const float scale = __expf(m - mn);   // m=-inf on first row -> 0
        const float wr    = __expf(sc - mn);
        den = den * scale + wr;

        a0.x = fmaf(wr, f0.x, a0.x * scale); a0.y = fmaf(wr, f0.y, a0.y * scale);
        a0.z = fmaf(wr, f0.z, a0.z * scale); a0.w = fmaf(wr, f0.w, a0.w * scale);
        a1.x = fmaf(wr, f1.x, a1.x * scale); a1.y = fmaf(wr, f1.y, a1.y * scale);
        a1.z = fmaf(wr, f1.z, a1.z * scale); a1.w = fmaf(wr, f1.w, a1.w * scale);
        a2.x = fmaf(wr, f2.x, a2.x * scale); a2.y = fmaf(wr, f2.y, a2.y * scale);
        a2.z = fmaf(wr, f2.z, a2.z * scale); a2.w = fmaf(wr, f2.w, a2.w * scale);
        a3.x = fmaf(wr, f3.x, a3.x * scale); a3.y = fmaf(wr, f3.y, a3.y * scale);
        a3.z = fmaf(wr, f3.z, a3.z * scale); a3.w = fmaf(wr, f3.w, a3.w * scale);

        m = mn;

        if (has_next) { f0 = g0; f1 = g1; f2 = g2; f3 = g3; }
    }

    const float inv = 1.0f / den;
    a0.x *= inv; a0.y *= inv; a0.z *= inv; a0.w *= inv;
    a1.x *= inv; a1.y *= inv; a1.z *= inv; a1.w *= inv;
    a2.x *= inv; a2.y *= inv; a2.z *= inv; a2.w *= inv;
    a3.x *= inv; a3.y *= inv; a3.z *= inv; a3.w *= inv;
    orow4[lane]      = a0;
    orow4[32 + lane] = a1;
    orow4[64 + lane] = a2;
    orow4[96 + lane] = a3;
}

// ---------------------------------------------------------------------------
// Launch
// Inputs: features [N,512] f32, residue_index [N] int32,
//         proj_w [512,512] f32, proj_b [512] f32, query [512] f32
// Output: [NSEG, 512] f32
// ---------------------------------------------------------------------------
extern "C" void kernel_launch(void* const* d_in, const int* in_sizes, int n_in,
                              void* d_out, int out_size) {
    const float* features = (const float*)d_in[0];
    const int*   ridx     = (const int*)d_in[1];
    const float* proj_w   = (const float*)d_in[2];
    const float* proj_b   = (const float*)d_in[3];
    const float* query    = (const float*)d_in[4];
    float*       out      = (float*)d_out;

    const int n_atoms = in_sizes[1];
    const int nseg    = out_size / FEAT;

    const int off_blks = (n_atoms + 255) / 256;
    setup_kernel<<<VPART_BLKS + off_blks, 256>>>(proj_w, query, ridx, n_atoms, nseg);
    compute_v_final_kernel<<<1, FEAT>>>(proj_b, query);

    const int nblk = (nseg + WARPS_PER_BLK - 1) / WARPS_PER_BLK;
    warp_pool_kernel<<<nblk, WARPS_PER_BLK * 32>>>(features, out, nseg);
}

// round 5
// speedup vs baseline: 1.1219x; 1.1219x over previous
#include <cuda_runtime.h>
#include <math.h>

#define FEAT       512
#define FEAT4      128            // FEAT / 4
#define MAX_NSEG   65536
#define VPART_BLKS 32
#define E_PER_BLK  16             // FEAT / VPART_BLKS

__device__ float g_v[FEAT];
__device__ float g_vpart[VPART_BLKS * FEAT];
__device__ float g_c;
__device__ int   g_seg_start[MAX_NSEG + 1];

// ---------------------------------------------------------------------------
// Kernel A (fused setup): blocks [0, VPART_BLKS) compute partial v = W^T q;
// blocks [VPART_BLKS, ...) build segment start offsets from sorted int32 idx.
// ---------------------------------------------------------------------------
__global__ __launch_bounds__(256)
void setup_kernel(const float* __restrict__ W,
                  const float* __restrict__ q,
                  const int* __restrict__ idx,
                  int n, int nseg) {
    const int b = blockIdx.x;
    if (b < VPART_BLKS) {
        #pragma unroll
        for (int half = 0; half < 2; half++) {
            const int d = threadIdx.x + half * 256;
            float acc = 0.0f;
            #pragma unroll
            for (int i = 0; i < E_PER_BLK; i++) {
                int e = b * E_PER_BLK + i;
                acc = fmaf(W[(size_t)e * FEAT + d], __ldg(&q[e]), acc);
            }
            g_vpart[b * FEAT + d] = acc;
        }
    } else {
        const int i = (b - VPART_BLKS) * 256 + threadIdx.x;
        if (i >= n) return;
        int cur  = idx[i];
        int prev = (i == 0) ? -1 : idx[i - 1];
        if (cur  > nseg) cur  = nseg;
        if (prev > nseg) prev = nseg;
        for (int s = prev + 1; s <= cur; s++) g_seg_start[s] = i;
        if (i == n - 1) {
            for (int s = cur + 1; s <= nseg; s++) g_seg_start[s] = n;
        }
    }
}

// ---------------------------------------------------------------------------
// Kernel B: reduce partials -> g_v;  c = b . q
// ---------------------------------------------------------------------------
__global__ __launch_bounds__(FEAT)
void compute_v_final_kernel(const float* __restrict__ b,
                            const float* __restrict__ q) {
    const int d = threadIdx.x;
    float acc = 0.0f;
    #pragma unroll
    for (int p = 0; p < VPART_BLKS; p++) acc += g_vpart[p * FEAT + d];
    g_v[d] = acc;

    __shared__ float red[FEAT];
    red[d] = b[d] * q[d];
    __syncthreads();
    for (int s = FEAT / 2; s > 0; s >>= 1) {
        if (d < s) red[d] += red[d + s];
        __syncthreads();
    }
    if (d == 0) g_c = red[0];
}

// ---------------------------------------------------------------------------
// Kernel C: warp-per-segment online-softmax attention pooling.
// Rows processed in PAIRS: both rows' 8x LDG.128 issue back-to-back (MLP=8),
// the two independent warp-allreduce chains interleave, then one joint
// online-softmax update (fewer accumulator rescales than two serial updates).
// No __syncthreads, no atomics, features read exactly once.
// ---------------------------------------------------------------------------
#define WARPS_PER_BLK 8

__global__ __launch_bounds__(WARPS_PER_BLK * 32)
void warp_pool_kernel(const float* __restrict__ feat,
                      float* __restrict__ out,
                      int nseg) {
    const int wid  = threadIdx.x >> 5;
    const int lane = threadIdx.x & 31;
    const int s    = blockIdx.x * WARPS_PER_BLK + wid;
    if (s >= nseg) return;

    const int start = g_seg_start[s];
    const int end   = g_seg_start[s + 1];

    float4* orow4 = (float4*)(out + (size_t)s * FEAT);

    if (start >= end) {
        const float4 z = make_float4(0.f, 0.f, 0.f, 0.f);
        orow4[lane] = z; orow4[32 + lane] = z; orow4[64 + lane] = z; orow4[96 + lane] = z;
        return;
    }

    // register-resident v slice
    const float4* v4 = (const float4*)g_v;
    const float4 v0 = v4[lane];
    const float4 v1 = v4[32 + lane];
    const float4 v2 = v4[64 + lane];
    const float4 v3 = v4[96 + lane];
    const float  c  = g_c;

    float m   = -INFINITY;
    float den = 0.0f;
    float4 a0 = make_float4(0.f, 0.f, 0.f, 0.f);
    float4 a1 = a0, a2 = a0, a3 = a0;

    const float4* feat4 = (const float4*)feat;

    int r = start;
    for (; r + 1 < end; r += 2) {
        // ---- both rows' loads issue before any dependent compute ----
        const float4* rowA = feat4 + (size_t)r * FEAT4;
        const float4* rowB = rowA + FEAT4;
        float4 f0 = rowA[lane];
        float4 f1 = rowA[32 + lane];
        float4 f2 = rowA[64 + lane];
        float4 f3 = rowA[96 + lane];
        float4 g0 = rowB[lane];
        float4 g1 = rowB[32 + lane];
        float4 g2 = rowB[64 + lane];
        float4 g3 = rowB[96 + lane];

        // ---- two independent dot products ----
        float p0 = f0.x * v0.x, p1 = g0.x * v0.x;
        p0 = fmaf(f0.y, v0.y, p0); p1 = fmaf(g0.y, v0.y, p1);
        p0 = fmaf(f0.z, v0.z, p0); p1 = fmaf(g0.z, v0.z, p1);
        p0 = fmaf(f0.w, v0.w, p0); p1 = fmaf(g0.w, v0.w, p1);
        p0 = fmaf(f1.x, v1.x, p0); p1 = fmaf(g1.x, v1.x, p1);
        p0 = fmaf(f1.y, v1.y, p0); p1 = fmaf(g1.y, v1.y, p1);
        p0 = fmaf(f1.z, v1.z, p0); p1 = fmaf(g1.z, v1.z, p1);
        p0 = fmaf(f1.w, v1.w, p0); p1 = fmaf(g1.w, v1.w, p1);
        p0 = fmaf(f2.x, v2.x, p0); p1 = fmaf(g2.x, v2.x, p1);
        p0 = fmaf(f2.y, v2.y, p0); p1 = fmaf(g2.y, v2.y, p1);
        p0 = fmaf(f2.z, v2.z, p0); p1 = fmaf(g2.z, v2.z, p1);
        p0 = fmaf(f2.w, v2.w, p0); p1 = fmaf(g2.w, v2.w, p1);
        p0 = fmaf(f3.x, v3.x, p0); p1 = fmaf(g3.x, v3.x, p1);
        p0 = fmaf(f3.y, v3.y, p0); p1 = fmaf(g3.y, v3.y, p1);
        p0 = fmaf(f3.z, v3.z, p0); p1 = fmaf(g3.z, v3.z, p1);
        p0 = fmaf(f3.w, v3.w, p0); p1 = fmaf(g3.w, v3.w, p1);

        // ---- interleaved warp allreduces (independent shfl chains) ----
        #pragma unroll
        for (int o = 16; o > 0; o >>= 1) {
            p0 += __shfl_xor_sync(0xffffffffu, p0, o);
            p1 += __shfl_xor_sync(0xffffffffu, p1, o);
        }

        // ---- joint online softmax update for both rows ----
        const float sc0 = p0 + c;
        const float sc1 = p1 + c;
        const float mn  = fmaxf(m, fmaxf(sc0, sc1));
        const float scale = __expf(m - mn);     // m=-inf initially -> 0
        const float w0  = __expf(sc0 - mn);
        const float w1  = __expf(sc1 - mn);
        den = fmaf(den, scale, w0 + w1);

        a0.x = fmaf(w1, g0.x, fmaf(w0, f0.x, a0.x * scale));
        a0.y = fmaf(w1, g0.y, fmaf(w0, f0.y, a0.y * scale));
        a0.z = fmaf(w1, g0.z, fmaf(w0, f0.z, a0.z * scale));
        a0.w = fmaf(w1, g0.w, fmaf(w0, f0.w, a0.w * scale));
        a1.x = fmaf(w1, g1.x, fmaf(w0, f1.x, a1.x * scale));
        a1.y = fmaf(w1, g1.y, fmaf(w0, f1.y, a1.y * scale));
        a1.z = fmaf(w1, g1.z, fmaf(w0, f1.z, a1.z * scale));
        a1.w = fmaf(w1, g1.w, fmaf(w0, f1.w, a1.w * scale));
        a2.x = fmaf(w1, g2.x, fmaf(w0, f2.x, a2.x * scale));
        a2.y = fmaf(w1, g2.y, fmaf(w0, f2.y, a2.y * scale));
        a2.z = fmaf(w1, g2.z, fmaf(w0, f2.z, a2.z * scale));
        a2.w = fmaf(w1, g2.w, fmaf(w0, f2.w, a2.w * scale));
        a3.x = fmaf(w1, g3.x, fmaf(w0, f3.x, a3.x * scale));
        a3.y = fmaf(w1, g3.y, fmaf(w0, f3.y, a3.y * scale));
        a3.z = fmaf(w1, g3.z, fmaf(w0, f3.z, a3.z * scale));
        a3.w = fmaf(w1, g3.w, fmaf(w0, f3.w, a3.w * scale));

        m = mn;
    }

    // ---- tail: at most one leftover row ----
    if (r < end) {
        const float4* row = feat4 + (size_t)r * FEAT4;
        float4 f0 = row[lane];
        float4 f1 = row[32 + lane];
        float4 f2 = row[64 + lane];
        float4 f3 = row[96 + lane];

        float p = f0.x * v0.x;
        p = fmaf(f0.y, v0.y, p); p = fmaf(f0.z, v0.z, p); p = fmaf(f0.w, v0.w, p);
        p = fmaf(f1.x, v1.x, p); p = fmaf(f1.y, v1.y, p); p = fmaf(f1.z, v1.z, p); p = fmaf(f1.w, v1.w, p);
        p = fmaf(f2.x, v2.x, p); p = fmaf(f2.y, v2.y, p); p = fmaf(f2.z, v2.z, p); p = fmaf(f2.w, v2.w, p);
        p = fmaf(f3.x, v3.x, p); p = fmaf(f3.y, v3.y, p); p = fmaf(f3.z, v3.z, p); p = fmaf(f3.w, v3.w, p);

        #pragma unroll
        for (int o = 16; o > 0; o >>= 1)
            p += __shfl_xor_sync(0xffffffffu, p, o);

        const float sc    = p + c;
        const float mn    = fmaxf(m, sc);
        const float scale = __expf(m - mn);
        const float wr    = __expf(sc - mn);
        den = fmaf(den, scale, wr);

        a0.x = fmaf(wr, f0.x, a0.x * scale); a0.y = fmaf(wr, f0.y, a0.y * scale);
        a0.z = fmaf(wr, f0.z, a0.z * scale); a0.w = fmaf(wr, f0.w, a0.w * scale);
        a1.x = fmaf(wr, f1.x, a1.x * scale); a1.y = fmaf(wr, f1.y, a1.y * scale);
        a1.z = fmaf(wr, f1.z, a1.z * scale); a1.w = fmaf(wr, f1.w, a1.w * scale);
        a2.x = fmaf(wr, f2.x, a2.x * scale); a2.y = fmaf(wr, f2.y, a2.y * scale);
        a2.z = fmaf(wr, f2.z, a2.z * scale); a2.w = fmaf(wr, f2.w, a2.w * scale);
        a3.x = fmaf(wr, f3.x, a3.x * scale); a3.y = fmaf(wr, f3.y, a3.y * scale);
        a3.z = fmaf(wr, f3.z, a3.z * scale); a3.w = fmaf(wr, f3.w, a3.w * scale);
    }

    const float inv = 1.0f / den;
    a0.x *= inv; a0.y *= inv; a0.z *= inv; a0.w *= inv;
    a1.x *= inv; a1.y *= inv; a1.z *= inv; a1.w *= inv;
    a2.x *= inv; a2.y *= inv; a2.z *= inv; a2.w *= inv;
    a3.x *= inv; a3.y *= inv; a3.z *= inv; a3.w *= inv;
    orow4[lane]      = a0;
    orow4[32 + lane] = a1;
    orow4[64 + lane] = a2;
    orow4[96 + lane] = a3;
}

// ---------------------------------------------------------------------------
// Launch
// Inputs: features [N,512] f32, residue_index [N] int32,
//         proj_w [512,512] f32, proj_b [512] f32, query [512] f32
// Output: [NSEG, 512] f32
// ---------------------------------------------------------------------------
extern "C" void kernel_launch(void* const* d_in, const int* in_sizes, int n_in,
                              void* d_out, int out_size) {
    const float* features = (const float*)d_in[0];
    const int*   ridx     = (const int*)d_in[1];
    const float* proj_w   = (const float*)d_in[2];
    const float* proj_b   = (const float*)d_in[3];
    const float* query    = (const float*)d_in[4];
    float*       out      = (float*)d_out;

    const int n_atoms = in_sizes[1];
    const int nseg    = out_size / FEAT;

    const int off_blks = (n_atoms + 255) / 256;
    setup_kernel<<<VPART_BLKS + off_blks, 256>>>(proj_w, query, ridx, n_atoms, nseg);
    compute_v_final_kernel<<<1, FEAT>>>(proj_b, query);

    const int nblk = (nseg + WARPS_PER_BLK - 1) / WARPS_PER_BLK;
    warp_pool_kernel<<<nblk, WARPS_PER_BLK * 32>>>(features, out, nseg);
}

// round 6
// speedup vs baseline: 1.1421x; 1.0180x over previous
#include <cuda_runtime.h>
#include <math.h>

#define FEAT       512
#define FEAT4      128            // FEAT / 4
#define MAX_NSEG   65536
#define VPART_BLKS 32
#define E_PER_BLK  16             // FEAT / VPART_BLKS

__device__ float g_v[FEAT];
__device__ float g_vpart[VPART_BLKS * FEAT];
__device__ float g_c;
__device__ int   g_seg_start[MAX_NSEG + 1];
__device__ int   g_done;          // zero-initialized; reset by reducer each launch

// ---------------------------------------------------------------------------
// Kernel A (fused setup, single launch):
//   blocks [0, VPART_BLKS)            : partial v = W^T q  (+ done-counter)
//   blocks [VPART_BLKS, VPART+off)    : segment start offsets (sorted int32 idx)
//   block  VPART_BLKS + off_blks      : spin on counter, reduce partials -> g_v,
//                                       c = b.q, reset counter for next replay
// ---------------------------------------------------------------------------
__global__ __launch_bounds__(256)
void setup_kernel(const float* __restrict__ W,
                  const float* __restrict__ q,
                  const float* __restrict__ bias,
                  const int* __restrict__ idx,
                  int n, int nseg, int off_blks) {
    const int b = blockIdx.x;
    if (b < VPART_BLKS) {
        #pragma unroll
        for (int half = 0; half < 2; half++) {
            const int d = threadIdx.x + half * 256;
            float acc = 0.0f;
            #pragma unroll
            for (int i = 0; i < E_PER_BLK; i++) {
                int e = b * E_PER_BLK + i;
                acc = fmaf(W[(size_t)e * FEAT + d], __ldg(&q[e]), acc);
            }
            g_vpart[b * FEAT + d] = acc;
        }
        __threadfence();
        __syncthreads();
        if (threadIdx.x == 0) atomicAdd(&g_done, 1);
    } else if (b < VPART_BLKS + off_blks) {
        const int i = (b - VPART_BLKS) * 256 + threadIdx.x;
        if (i >= n) return;
        int cur  = idx[i];
        int prev = (i == 0) ? -1 : idx[i - 1];
        if (cur  > nseg) cur  = nseg;
        if (prev > nseg) prev = nseg;
        for (int s = prev + 1; s <= cur; s++) g_seg_start[s] = i;
        if (i == n - 1) {
            for (int s = cur + 1; s <= nseg; s++) g_seg_start[s] = n;
        }
    } else {
        // reducer block: wait for all vpart blocks of THIS launch
        if (threadIdx.x == 0) {
            while (atomicAdd(&g_done, 0) < VPART_BLKS) { }
        }
        __syncthreads();

        #pragma unroll
        for (int half = 0; half < 2; half++) {
            const int d = threadIdx.x + half * 256;
            float acc = 0.0f;
            #pragma unroll
            for (int p = 0; p < VPART_BLKS; p++) acc += g_vpart[p * FEAT + d];
            g_v[d] = acc;
        }

        // c = bias . q  (256 threads, 2 elements each)
        __shared__ float red[256];
        const int t = threadIdx.x;
        red[t] = bias[t] * q[t] + bias[t + 256] * q[t + 256];
        __syncthreads();
        for (int s = 128; s > 0; s >>= 1) {
            if (t < s) red[t] += red[t + s];
            __syncthreads();
        }
        if (t == 0) {
            g_c = red[0];
            g_done = 0;   // reset for next graph replay (stream-serialized)
        }
    }
}

// ---------------------------------------------------------------------------
// Kernel B: warp-per-segment online-softmax attention pooling.
// Rows processed in PAIRS: both rows' 8x LDG.128 (streaming, evict-first)
// issue back-to-back, two independent warp-allreduce chains interleave, then
// one joint online-softmax update. No __syncthreads, no atomics, features
// read exactly once.
// ---------------------------------------------------------------------------
#define WARPS_PER_BLK 8

__device__ __forceinline__ float4 ldcs4(const float4* p) {
    return __ldcs(p);
}

__global__ __launch_bounds__(WARPS_PER_BLK * 32)
void warp_pool_kernel(const float* __restrict__ feat,
                      float* __restrict__ out,
                      int nseg) {
    const int wid  = threadIdx.x >> 5;
    const int lane = threadIdx.x & 31;
    const int s    = blockIdx.x * WARPS_PER_BLK + wid;
    if (s >= nseg) return;

    const int start = g_seg_start[s];
    const int end   = g_seg_start[s + 1];

    float4* orow4 = (float4*)(out + (size_t)s * FEAT);

    if (start >= end) {
        const float4 z = make_float4(0.f, 0.f, 0.f, 0.f);
        __stcs(&orow4[lane], z);
        __stcs(&orow4[32 + lane], z);
        __stcs(&orow4[64 + lane], z);
        __stcs(&orow4[96 + lane], z);
        return;
    }

    // register-resident v slice (L2-resident after first block)
    const float4* v4 = (const float4*)g_v;
    const float4 v0 = v4[lane];
    const float4 v1 = v4[32 + lane];
    const float4 v2 = v4[64 + lane];
    const float4 v3 = v4[96 + lane];
    const float  c  = g_c;

    float m   = -INFINITY;
    float den = 0.0f;
    float4 a0 = make_float4(0.f, 0.f, 0.f, 0.f);
    float4 a1 = a0, a2 = a0, a3 = a0;

    const float4* feat4 = (const float4*)feat;

    int r = start;
    for (; r + 1 < end; r += 2) {
        // ---- both rows' loads issue before any dependent compute ----
        const float4* rowA = feat4 + (size_t)r * FEAT4;
        const float4* rowB = rowA + FEAT4;
        float4 f0 = ldcs4(&rowA[lane]);
        float4 f1 = ldcs4(&rowA[32 + lane]);
        float4 f2 = ldcs4(&rowA[64 + lane]);
        float4 f3 = ldcs4(&rowA[96 + lane]);
        float4 g0 = ldcs4(&rowB[lane]);
        float4 g1 = ldcs4(&rowB[32 + lane]);
        float4 g2 = ldcs4(&rowB[64 + lane]);
        float4 g3 = ldcs4(&rowB[96 + lane]);

        // ---- two independent dot products ----
        float p0 = f0.x * v0.x, p1 = g0.x * v0.x;
        p0 = fmaf(f0.y, v0.y, p0); p1 = fmaf(g0.y, v0.y, p1);
        p0 = fmaf(f0.z, v0.z, p0); p1 = fmaf(g0.z, v0.z, p1);
        p0 = fmaf(f0.w, v0.w, p0); p1 = fmaf(g0.w, v0.w, p1);
        p0 = fmaf(f1.x, v1.x, p0); p1 = fmaf(g1.x, v1.x, p1);
        p0 = fmaf(f1.y, v1.y, p0); p1 = fmaf(g1.y, v1.y, p1);
        p0 = fmaf(f1.z, v1.z, p0); p1 = fmaf(g1.z, v1.z, p1);
        p0 = fmaf(f1.w, v1.w, p0); p1 = fmaf(g1.w, v1.w, p1);
        p0 = fmaf(f2.x, v2.x, p0); p1 = fmaf(g2.x, v2.x, p1);
        p0 = fmaf(f2.y, v2.y, p0); p1 = fmaf(g2.y, v2.y, p1);
        p0 = fmaf(f2.z, v2.z, p0); p1 = fmaf(g2.z, v2.z, p1);
        p0 = fmaf(f2.w, v2.w, p0); p1 = fmaf(g2.w, v2.w, p1);
        p0 = fmaf(f3.x, v3.x, p0); p1 = fmaf(g3.x, v3.x, p1);
        p0 = fmaf(f3.y, v3.y, p0); p1 = fmaf(g3.y, v3.y, p1);
        p0 = fmaf(f3.z, v3.z, p0); p1 = fmaf(g3.z, v3.z, p1);
        p0 = fmaf(f3.w, v3.w, p0); p1 = fmaf(g3.w, v3.w, p1);

        // ---- interleaved warp allreduces (independent shfl chains) ----
        #pragma unroll
        for (int o = 16; o > 0; o >>= 1) {
            p0 += __shfl_xor_sync(0xffffffffu, p0, o);
            p1 += __shfl_xor_sync(0xffffffffu, p1, o);
        }

        // ---- joint online softmax update for both rows ----
        const float sc0 = p0 + c;
        const float sc1 = p1 + c;
        const float mn  = fmaxf(m, fmaxf(sc0, sc1));
        const float scale = __expf(m - mn);     // m=-inf initially -> 0
        const float w0  = __expf(sc0 - mn);
        const float w1  = __expf(sc1 - mn);
        den = fmaf(den, scale, w0 + w1);

        a0.x = fmaf(w1, g0.x, fmaf(w0, f0.x, a0.x * scale));
        a0.y = fmaf(w1, g0.y, fmaf(w0, f0.y, a0.y * scale));
        a0.z = fmaf(w1, g0.z, fmaf(w0, f0.z, a0.z * scale));
        a0.w = fmaf(w1, g0.w, fmaf(w0, f0.w, a0.w * scale));
        a1.x = fmaf(w1, g1.x, fmaf(w0, f1.x, a1.x * scale));
        a1.y = fmaf(w1, g1.y, fmaf(w0, f1.y, a1.y * scale));
        a1.z = fmaf(w1, g1.z, fmaf(w0, f1.z, a1.z * scale));
        a1.w = fmaf(w1, g1.w, fmaf(w0, f1.w, a1.w * scale));
        a2.x = fmaf(w1, g2.x, fmaf(w0, f2.x, a2.x * scale));
        a2.y = fmaf(w1, g2.y, fmaf(w0, f2.y, a2.y * scale));
        a2.z = fmaf(w1, g2.z, fmaf(w0, f2.z, a2.z * scale));
        a2.w = fmaf(w1, g2.w, fmaf(w0, f2.w, a2.w * scale));
        a3.x = fmaf(w1, g3.x, fmaf(w0, f3.x, a3.x * scale));
        a3.y = fmaf(w1, g3.y, fmaf(w0, f3.y, a3.y * scale));
        a3.z = fmaf(w1, g3.z, fmaf(w0, f3.z, a3.z * scale));
        a3.w = fmaf(w1, g3.w, fmaf(w0, f3.w, a3.w * scale));

        m = mn;
    }

    // ---- tail: at most one leftover row ----
    if (r < end) {
        const float4* row = feat4 + (size_t)r * FEAT4;
        float4 f0 = ldcs4(&row[lane]);
        float4 f1 = ldcs4(&row[32 + lane]);
        float4 f2 = ldcs4(&row[64 + lane]);
        float4 f3 = ldcs4(&row[96 + lane]);

        float p = f0.x * v0.x;
        p = fmaf(f0.y, v0.y, p); p = fmaf(f0.z, v0.z, p); p = fmaf(f0.w, v0.w, p);
        p = fmaf(f1.x, v1.x, p); p = fmaf(f1.y, v1.y, p); p = fmaf(f1.z, v1.z, p); p = fmaf(f1.w, v1.w, p);
        p = fmaf(f2.x, v2.x, p); p = fmaf(f2.y, v2.y, p); p = fmaf(f2.z, v2.z, p); p = fmaf(f2.w, v2.w, p);
        p = fmaf(f3.x, v3.x, p); p = fmaf(f3.y, v3.y, p); p = fmaf(f3.z, v3.z, p); p = fmaf(f3.w, v3.w, p);

        #pragma unroll
        for (int o = 16; o > 0; o >>= 1)
            p += __shfl_xor_sync(0xffffffffu, p, o);

        const float sc    = p + c;
        const float mn    = fmaxf(m, sc);
        const float scale = __expf(m - mn);
        const float wr    = __expf(sc - mn);
        den = fmaf(den, scale, wr);

        a0.x = fmaf(wr, f0.x, a0.x * scale); a0.y = fmaf(wr, f0.y, a0.y * scale);
        a0.z = fmaf(wr, f0.z, a0.z * scale); a0.w = fmaf(wr, f0.w, a0.w * scale);
        a1.x = fmaf(wr, f1.x, a1.x * scale); a1.y = fmaf(wr, f1.y, a1.y * scale);
        a1.z = fmaf(wr, f1.z, a1.z * scale); a1.w = fmaf(wr, f1.w, a1.w * scale);
        a2.x = fmaf(wr, f2.x, a2.x * scale); a2.y = fmaf(wr, f2.y, a2.y * scale);
        a2.z = fmaf(wr, f2.z, a2.z * scale); a2.w = fmaf(wr, f2.w, a2.w * scale);
        a3.x = fmaf(wr, f3.x, a3.x * scale); a3.y = fmaf(wr, f3.y, a3.y * scale);
        a3.z = fmaf(wr, f3.z, a3.z * scale); a3.w = fmaf(wr, f3.w, a3.w * scale);
    }

    const float inv = 1.0f / den;
    a0.x *= inv; a0.y *= inv; a0.z *= inv; a0.w *= inv;
    a1.x *= inv; a1.y *= inv; a1.z *= inv; a1.w *= inv;
    a2.x *= inv; a2.y *= inv; a2.z *= inv; a2.w *= inv;
    a3.x *= inv; a3.y *= inv; a3.z *= inv; a3.w *= inv;
    __stcs(&orow4[lane],      a0);
    __stcs(&orow4[32 + lane], a1);
    __stcs(&orow4[64 + lane], a2);
    __stcs(&orow4[96 + lane], a3);
}

// ---------------------------------------------------------------------------
// Launch
// Inputs: features [N,512] f32, residue_index [N] int32,
//         proj_w [512,512] f32, proj_b [512] f32, query [512] f32
// Output: [NSEG, 512] f32
// ---------------------------------------------------------------------------
extern "C" void kernel_launch(void* const* d_in, const int* in_sizes, int n_in,
                              void* d_out, int out_size) {
    const float* features = (const float*)d_in[0];
    const int*   ridx     = (const int*)d_in[1];
    const float* proj_w   = (const float*)d_in[2];
    const float* proj_b   = (const float*)d_in[3];
    const float* query    = (const float*)d_in[4];
    float*       out      = (float*)d_out;

    const int n_atoms = in_sizes[1];
    const int nseg    = out_size / FEAT;

    const int off_blks = (n_atoms + 255) / 256;
    setup_kernel<<<VPART_BLKS + off_blks + 1, 256>>>(proj_w, query, proj_b,
                                                     ridx, n_atoms, nseg, off_blks);

    const int nblk = (nseg + WARPS_PER_BLK - 1) / WARPS_PER_BLK;
    warp_pool_kernel<<<nblk, WARPS_PER_BLK * 32>>>(features, out, nseg);
}